// round 11
// baseline (speedup 1.0000x reference)
#include <cuda_runtime.h>
#include <cstdint>

#define H 256
#define W 256
#define K 512
#define Z_THRESHOLD 3.0f
#define EPS 1e-08f

// sqrt(0.5 * log2(e)): folded into inverse scales so gauss = exp2(-(dx'^2+dy'^2))
#define SCALE_C 0.84932180028801904f

#define RTPB  256            // render threads per block (1 image row)
#define NWARP (RTPB / 32)

// Cull threshold: max row alpha < 2^-20 ~ 1e-6 -> skipped gaussian perturbs
// a pixel by < ~6e-5 absolute; rel tolerance is 1e-3.
#define CULL_LOG2 -20.0f

// Global sorted-survivor params (device globals: no allocation allowed)
__device__ float4 gA[K];   // isx', -px*isx', isy', -py*isy'
__device__ float2 gB[K];   // log2(eff_w), intensity
__device__ int    gM;

// ---------------------------------------------------------------------------
// Kernel 1 (1 block, K threads): z-weights -> compact active keys -> rank
// sort (unique keys embed original idx -> exact stable argsort(-eff_w)) ->
// heavy per-gaussian math ONLY for the M survivors -> sorted params to gmem.
// ---------------------------------------------------------------------------
__global__ void __launch_bounds__(K, 1)
prep_kernel(const float* __restrict__ positions,   // [K,3]
            const float* __restrict__ scales,      // [K,3]
            const float* __restrict__ opacity,     // [K]
            const float* __restrict__ intensity,   // [K]
            const float* __restrict__ z_target)    // [1]
{
    __shared__ unsigned long long sk[K];
    __shared__ int sCnt;

    const int tid  = threadIdx.x;
    const int lane = tid & 31;

    if (tid == 0) sCnt = 0;

    // ---- z phase: effective weight ----
    const float zt = z_target[0];
    const float pz = positions[tid * 3 + 2];
    const float sz = scales[tid * 3 + 2];
    const float zd = __fdividef(zt - pz, sz + EPS);
    float w = 0.0f;
    if (fabsf(zd) < Z_THRESHOLD) {
        w = opacity[tid] * __expf(-0.5f * zd * zd);
    }

    // Ascending uint64 order == descending eff_w, ascending idx on ties
    // (stable argsort(-eff_w); keys unique via embedded idx).
    const unsigned int wb = __float_as_uint(w);    // w >= 0: bits monotone
    const unsigned long long key =
        ((unsigned long long)(~wb) << 32) | (unsigned int)tid;

    __syncthreads();   // sCnt = 0 visible

    // ---- compact active keys (order-free; rank sort fixes order) ----
    const bool active = (w > 0.0f);
    unsigned int mask = __ballot_sync(0xFFFFFFFFu, active);
    int base = 0;
    if (lane == 0 && mask) base = atomicAdd(&sCnt, __popc(mask));
    base = __shfl_sync(0xFFFFFFFFu, base, 0);
    if (active) {
        sk[base + __popc(mask & ((1u << lane) - 1u))] = key;
    }
    __syncthreads();

    const int M = sCnt;

    // ---- rank sort + heavy prep for survivors only ----
    if (tid < M) {
        const unsigned long long mykey = sk[tid];
        int rank = 0;
        for (int j = 0; j < M; ++j) {
            rank += (sk[j] < mykey);   // broadcast LDS, unique keys
        }
        const int   g  = (int)(mykey & 0xFFFFFFFFull);
        const float ws = __uint_as_float(~(unsigned int)(mykey >> 32));

        const float px  = positions[g * 3 + 0];
        const float py  = positions[g * 3 + 1];
        const float isx = __fdividef(SCALE_C, scales[g * 3 + 0] + EPS);
        const float isy = __fdividef(SCALE_C, scales[g * 3 + 1] + EPS);

        gA[rank] = make_float4(isx, -px * isx, isy, -py * isy);
        gB[rank] = make_float2(__log2f(ws), intensity[g]);
    }
    if (tid == 0) gM = M;
}

// ---------------------------------------------------------------------------
// Kernel 2 (H blocks, RTPB threads): one image row per block.
//   1) tile-scan the M sorted params, keep top = log2w - dx'^2 > CULL_LOG2,
//      order-preserving compaction into smem (warp-count scan, no atomics),
//   2) composite one pixel per thread over the ~8 survivors.
// 2 barriers per tile (M <= 256 -> one tile -> 2 barriers total).
// ---------------------------------------------------------------------------
__global__ void __launch_bounds__(RTPB)
render_kernel(float* __restrict__ out)
{
    __shared__ float4 csp[K];        // row-survivors: isy', -py*isy', top, inten
    __shared__ int    warpCnt[NWARP];

    const int tid  = threadIdx.x;
    const int lane = tid & 31;
    const int wid  = tid >> 5;
    const float fy = (float)blockIdx.x;      // image row
    const int M = gM;

    int tilebase = 0;   // consistent across threads (all sum the same counts)
    for (int bb = 0; bb < M; bb += RTPB) {
        const int i = bb + tid;
        bool keep = false;
        float4 A; float2 B; float top = 0.0f;
        if (i < M) {
            A = gA[i];
            B = gB[i];
            float dxp = fmaf(fy, A.x, A.y);       // (fy - px) * isx'
            top = fmaf(dxp, -dxp, B.x);           // log2w - dx'^2
            keep = (top > CULL_LOG2);
        }
        unsigned int mask = __ballot_sync(0xFFFFFFFFu, keep);
        if (lane == 0) warpCnt[wid] = __popc(mask);
        __syncthreads();

        int before = 0, total = 0;
        #pragma unroll
        for (int ww = 0; ww < NWARP; ++ww) {
            int c = warpCnt[ww];
            total += c;
            if (ww < wid) before += c;
        }
        if (keep) {
            int pos = tilebase + before + __popc(mask & ((1u << lane) - 1u));
            csp[pos] = make_float4(A.z, A.w, top, B.y);
        }
        tilebase += total;
        __syncthreads();   // csp complete / warpCnt reusable
    }
    const int Mc = tilebase;

    // ---- render: one pixel per thread ----
    const float fx = (float)tid;             // column (positions[:,1])

    float T = 1.0f;
    float A = 0.0f;

    #pragma unroll 4
    for (int j = 0; j < Mc; ++j) {
        const float4 P = csp[j];

        float dy  = fmaf(fx, P.x, P.y);      // (fx - py) * isy'
        float arg = fmaf(dy, -dy, P.z);      // top - dy'^2

        float ga;                            // == gauss * eff_w
        asm("ex2.approx.ftz.f32 %0, %1;" : "=f"(ga) : "f"(arg));

        float a  = fminf(ga, 0.99f);
        float ta = T * a;
        A = fmaf(ta, P.w, A);
        T -= ta;
    }

    out[blockIdx.x * W + tid] = A;
}

extern "C" void kernel_launch(void* const* d_in, const int* in_sizes, int n_in,
                              void* d_out, int out_size)
{
    const float* positions = (const float*)d_in[0];
    const float* scales    = (const float*)d_in[1];
    const float* opacity   = (const float*)d_in[2];
    const float* intensity = (const float*)d_in[3];
    const float* z_target  = (const float*)d_in[4];
    float* out = (float*)d_out;

    prep_kernel<<<1, K>>>(positions, scales, opacity, intensity, z_target);
    render_kernel<<<H, RTPB>>>(out);
}

// round 12
// speedup vs baseline: 1.3029x; 1.3029x over previous
#include <cuda_runtime.h>
#include <cstdint>

#define H 256
#define W 256
#define K 512
#define Z_THRESHOLD 3.0f
#define EPS 1e-08f

// sqrt(0.5 * log2(e)): folded into inverse scales so gauss = exp2(-(dx'^2+dy'^2))
#define SCALE_C 0.84932180028801904f

#define TPB   256            // threads per block (1 image row per block)
#define GPT   2              // gaussians per thread (K / TPB)
#define GRID  H              // 256 blocks, 2 resident per SM

// Cull threshold: max row alpha < 2^-20 ~ 1e-6 -> skipped gaussian perturbs
// a pixel by < ~6e-5 absolute; rel tolerance is 1e-3.
#define CULL_LOG2 -20.0f

// ---------------------------------------------------------------------------
// Fused kernel, thin-prep version. Each block owns ONE image row.
//   1) thin prep (all 512 gaussians): w via z-phase, log2w, and a
//      DIVISION-FREE row cull:  top > -20  <=>
//      C^2 (fy-px)^2 < (log2w + 20) (sx+EPS)^2.  Raw values staged in smem.
//   2) ballot-compact the ~8 survivor keys (keys embed original idx;
//      ascending uint64 == stable argsort(-eff_w) restricted to survivors),
//   3) rank sort over ~8 keys; ONLY survivor threads do the 2 divisions and
//      final param packing, scattered straight to csp[rank],
//   4) render: 1 px/thread, 7-instr inner loop.
// 3 barriers, heavy math on <=Mc threads, every loop tiny.
// ---------------------------------------------------------------------------
__global__ void __launch_bounds__(TPB, 2)
fused_kernel(const float* __restrict__ positions,   // [K,3]
             const float* __restrict__ scales,      // [K,3]
             const float* __restrict__ opacity,     // [K]
             const float* __restrict__ intensity,   // [K]
             const float* __restrict__ z_target,    // [1]
             float* __restrict__ out)               // [H*W]
{
    __shared__ float4 raw4[K];            // px, py, sx, sy (unsorted)
    __shared__ float2 raw2[K];            // log2(eff_w), intensity (unsorted)
    __shared__ unsigned long long sk[K];  // compacted survivor keys
    __shared__ float4 csp[K];             // rank-ordered survivor params
    __shared__ int    sCnt;

    const int tid  = threadIdx.x;
    const int lane = tid & 31;
    const float fy = (float)blockIdx.x;   // this block's image row

    if (tid == 0) sCnt = 0;

    // ---- thin prep + division-free cull for 2 gaussians per thread ----
    const float zt = z_target[0];
    bool  kp[GPT];
    unsigned long long kk[GPT];

    #pragma unroll
    for (int s = 0; s < GPT; ++s) {
        const int g = tid + s * TPB;                  // warp-coalesced
        const float px = positions[g * 3 + 0];
        const float py = positions[g * 3 + 1];
        const float pz = positions[g * 3 + 2];
        const float sx = scales[g * 3 + 0];
        const float sy = scales[g * 3 + 1];
        const float sz = scales[g * 3 + 2];
        const float op = opacity[g];
        const float in = intensity[g];

        const float zd = __fdividef(zt - pz, sz + EPS);
        float w = 0.0f;
        if (fabsf(zd) < Z_THRESHOLD) {
            w = op * __expf(-0.5f * zd * zd);
        }
        const float l2w = __log2f(w);                 // -inf when w == 0

        // Division-free row cull:
        //   top = l2w - (C(fy-px)/(sx+EPS))^2 > CULL_LOG2
        //   <=>  C^2 (fy-px)^2 < (l2w - CULL_LOG2) (sx+EPS)^2
        const float t   = (fy - px) * SCALE_C;
        const float sxe = sx + EPS;
        kp[s] = (t * t < (l2w - CULL_LOG2) * (sxe * sxe));  // false for w=0

        // Ascending uint64 order == descending eff_w, ascending idx on ties
        // (stable argsort(-eff_w); keys unique via embedded idx).
        const unsigned int wb = __float_as_uint(w);   // w >= 0: bits monotone
        kk[s] = ((unsigned long long)(~wb) << 32) | (unsigned int)g;

        raw4[g] = make_float4(px, py, sx, sy);
        raw2[g] = make_float2(l2w, in);
    }
    __syncthreads();   // sCnt=0 + raw staging visible

    // ---- ballot-compact survivor keys ----
    unsigned int m0 = __ballot_sync(0xFFFFFFFFu, kp[0]);
    unsigned int m1 = __ballot_sync(0xFFFFFFFFu, kp[1]);
    const int cnt = __popc(m0) + __popc(m1);
    int base = 0;
    if (lane == 0 && cnt) base = atomicAdd(&sCnt, cnt);
    base = __shfl_sync(0xFFFFFFFFu, base, 0);
    const unsigned int ltmask = (1u << lane) - 1u;
    if (kp[0]) sk[base + __popc(m0 & ltmask)] = kk[0];
    if (kp[1]) sk[base + __popc(m0) + __popc(m1 & ltmask)] = kk[1];
    __syncthreads();

    const int Mc = sCnt;

    // ---- rank sort over the Mc survivors + heavy math ONLY here ----
    if (tid < Mc) {
        const unsigned long long mykey = sk[tid];
        int rank = 0;
        for (int j = 0; j < Mc; ++j) {
            rank += (sk[j] < mykey);   // broadcast LDS, unique keys
        }
        const int g = (int)(mykey & 0xFFFFFFFFull);
        const float4 R = raw4[g];
        const float2 S = raw2[g];
        const float isx = __fdividef(SCALE_C, R.z + EPS);
        const float isy = __fdividef(SCALE_C, R.w + EPS);
        const float dxp = (fy - R.x) * isx;
        const float top = fmaf(dxp, -dxp, S.x);       // log2w - dx'^2
        csp[rank] = make_float4(isy, -R.y * isy, top, S.y);
    }
    __syncthreads();

    // ---- render: one pixel per thread ----
    const float fx = (float)tid;          // column (positions[:,1])

    float T = 1.0f;
    float A = 0.0f;

    #pragma unroll 4
    for (int j = 0; j < Mc; ++j) {
        const float4 P = csp[j];

        float dy  = fmaf(fx, P.x, P.y);        // (fx - py) * isy'
        float arg = fmaf(dy, -dy, P.z);        // top - dy'^2

        float ga;                              // == gauss * eff_w
        asm("ex2.approx.ftz.f32 %0, %1;" : "=f"(ga) : "f"(arg));

        float a  = fminf(ga, 0.99f);
        float ta = T * a;
        A = fmaf(ta, P.w, A);
        T -= ta;
    }

    out[blockIdx.x * W + tid] = A;
}

extern "C" void kernel_launch(void* const* d_in, const int* in_sizes, int n_in,
                              void* d_out, int out_size)
{
    const float* positions = (const float*)d_in[0];
    const float* scales    = (const float*)d_in[1];
    const float* opacity   = (const float*)d_in[2];
    const float* intensity = (const float*)d_in[3];
    const float* z_target  = (const float*)d_in[4];
    float* out = (float*)d_out;

    fused_kernel<<<GRID, TPB>>>(positions, scales, opacity, intensity,
                                z_target, out);
}